// round 11
// baseline (speedup 1.0000x reference)
#include <cuda_runtime.h>
#include <cuda_bf16.h>

// x: [B=32, C=256, W=56, H=56] fp32, contiguous.
// Groups of 4 consecutive channels. Keep elements that equal the group max AND are > 0,
// clamped to max_clamp; zero otherwise.
//
// Active L2-residency experiment (fixed for sm_103 ptxas: L2::evict_last requires
// the 256-bit .v8.b32 form). Loads pin the 102.8 MB input keep-longest in the
// ~126 MB L2; .cs (evict-first) stores drain the output without displacing it.
// If residency holds across graph replays, steady-state DRAM traffic ~halves.
//
// Geometry in v8 (8-float, 256-bit) units:
//   spatial plane per channel: 3136 floats = 392 v8 chunks
//   threads = 2048 groups * 392 = 802,816 = 3136 blocks x 256 (exact).

static constexpr int V8_PER_PLANE  = 392;
static constexpr int FLT_PER_PLANE = 3136;
static constexpr int FLT_PER_GROUP = 4 * FLT_PER_PLANE;  // 12544
static constexpr int TOTAL_THREADS = 2048 * V8_PER_PLANE;

struct F8 { float v[8]; };

__device__ __forceinline__ F8 ldg256_keep(const float* p) {
    unsigned r0, r1, r2, r3, r4, r5, r6, r7;
    asm volatile("ld.global.L2::evict_last.v8.b32 {%0,%1,%2,%3,%4,%5,%6,%7}, [%8];"
                 : "=r"(r0), "=r"(r1), "=r"(r2), "=r"(r3),
                   "=r"(r4), "=r"(r5), "=r"(r6), "=r"(r7)
                 : "l"(p));
    F8 f;
    f.v[0] = __uint_as_float(r0); f.v[1] = __uint_as_float(r1);
    f.v[2] = __uint_as_float(r2); f.v[3] = __uint_as_float(r3);
    f.v[4] = __uint_as_float(r4); f.v[5] = __uint_as_float(r5);
    f.v[6] = __uint_as_float(r6); f.v[7] = __uint_as_float(r7);
    return f;
}

__device__ __forceinline__ void stg256_cs(float* p, const F8& r) {
    asm volatile("st.global.cs.v8.f32 [%0], {%1,%2,%3,%4,%5,%6,%7,%8};"
                 :: "l"(p),
                    "f"(r.v[0]), "f"(r.v[1]), "f"(r.v[2]), "f"(r.v[3]),
                    "f"(r.v[4]), "f"(r.v[5]), "f"(r.v[6]), "f"(r.v[7])
                 : "memory");
}

__global__ __launch_bounds__(256) void CGM_16707422781821_kernel(
    const float* __restrict__ x,
    float* __restrict__ out,
    const float* __restrict__ max_clamp_p)
{
    int idx = blockIdx.x * blockDim.x + threadIdx.x;

    const float mc = __ldg(max_clamp_p);

    int gb = idx / V8_PER_PLANE;
    int s  = idx - gb * V8_PER_PLANE;
    long base = (long)gb * FLT_PER_GROUP + (long)s * 8;

    const float* xp = x + base;
    F8 c0 = ldg256_keep(xp);
    F8 c1 = ldg256_keep(xp + FLT_PER_PLANE);
    F8 c2 = ldg256_keep(xp + 2 * FLT_PER_PLANE);
    F8 c3 = ldg256_keep(xp + 3 * FLT_PER_PLANE);

    #pragma unroll
    for (int i = 0; i < 8; i++) {
        float m = fmaxf(fmaxf(c0.v[i], c1.v[i]), fmaxf(c2.v[i], c3.v[i]));
        float cl = fminf(m, mc);
        bool pos = (m > 0.0f);
        c0.v[i] = (pos && c0.v[i] == m) ? cl : 0.0f;
        c1.v[i] = (pos && c1.v[i] == m) ? cl : 0.0f;
        c2.v[i] = (pos && c2.v[i] == m) ? cl : 0.0f;
        c3.v[i] = (pos && c3.v[i] == m) ? cl : 0.0f;
    }

    float* op = out + base;
    stg256_cs(op, c0);
    stg256_cs(op + FLT_PER_PLANE, c1);
    stg256_cs(op + 2 * FLT_PER_PLANE, c2);
    stg256_cs(op + 3 * FLT_PER_PLANE, c3);
}

extern "C" void kernel_launch(void* const* d_in, const int* in_sizes, int n_in,
                              void* d_out, int out_size) {
    const float* x = (const float*)d_in[0];
    // d_in[1] = group_size (int32, == 4, baked into geometry)
    const float* max_clamp_p = (const float*)d_in[2];
    float* out = (float*)d_out;

    const int threads = 256;
    const int blocks = TOTAL_THREADS / threads;  // 3136, exact
    CGM_16707422781821_kernel<<<blocks, threads>>>(x, out, max_clamp_p);
}

// round 12
// speedup vs baseline: 1.0082x; 1.0082x over previous
#include <cuda_runtime.h>
#include <cuda_bf16.h>

// x: [B=32, C=256, W=56, H=56] fp32, contiguous.
// Groups of 4 consecutive channels. Keep elements that equal the group max AND are > 0,
// clamped to max_clamp; zero otherwise.
//
// FINAL: pure-streaming float4 kernel, default cache policy on both streams.
// Eight structural/cache variants all measured 35.0-37.3 us; this form (high
// occupancy, 4x LDG.128 + 4x STG.128, default caching) was fastest at 34.98 us.
// Steady-state 205.5 MB/iter at ~5.9 TB/s effective = the sm_103a mixed r/w HBM
// floor for this working set. DRAM-bound; compute pipes idle by design.
//
// Geometry (float4 units):
//   spatial plane per channel: 56*56 = 3136 floats = 784 float4
//   one channel-group (4 channels) = 3136 float4, contiguous
//   threads = 2048 groups * 784 = 1,605,632 = 6272 blocks x 256 (exact, no tail)

static constexpr int F4_PER_PLANE = 784;
static constexpr int F4_PER_GROUP = 3136;
static constexpr int TOTAL_THREADS = 2048 * F4_PER_PLANE;  // 1,605,632

__global__ __launch_bounds__(256) void CGM_16707422781821_kernel(
    const float4* __restrict__ x,
    float4* __restrict__ out,
    const float* __restrict__ max_clamp_p)
{
    int idx = blockIdx.x * blockDim.x + threadIdx.x;   // grid is exact; no bounds check

    const float mc = __ldg(max_clamp_p);

    int gb = idx / F4_PER_PLANE;
    int s  = idx - gb * F4_PER_PLANE;
    long base = (long)gb * F4_PER_GROUP + s;

    float4 v0 = x[base];
    float4 v1 = x[base + F4_PER_PLANE];
    float4 v2 = x[base + 2 * F4_PER_PLANE];
    float4 v3 = x[base + 3 * F4_PER_PLANE];

    float mx_x = fmaxf(fmaxf(v0.x, v1.x), fmaxf(v2.x, v3.x));
    float mx_y = fmaxf(fmaxf(v0.y, v1.y), fmaxf(v2.y, v3.y));
    float mx_z = fmaxf(fmaxf(v0.z, v1.z), fmaxf(v2.z, v3.z));
    float mx_w = fmaxf(fmaxf(v0.w, v1.w), fmaxf(v2.w, v3.w));

    #define MASK1(v, m) (((v) == (m) && (v) > 0.0f) ? fminf((v), mc) : 0.0f)
    #define MASK4(v) do { \
        v.x = MASK1(v.x, mx_x); \
        v.y = MASK1(v.y, mx_y); \
        v.z = MASK1(v.z, mx_z); \
        v.w = MASK1(v.w, mx_w); \
    } while (0)

    MASK4(v0);
    MASK4(v1);
    MASK4(v2);
    MASK4(v3);

    out[base]                    = v0;
    out[base + F4_PER_PLANE]     = v1;
    out[base + 2 * F4_PER_PLANE] = v2;
    out[base + 3 * F4_PER_PLANE] = v3;

    #undef MASK4
    #undef MASK1
}

extern "C" void kernel_launch(void* const* d_in, const int* in_sizes, int n_in,
                              void* d_out, int out_size) {
    const float4* x = (const float4*)d_in[0];
    // d_in[1] = group_size (int32, == 4, baked into geometry)
    const float* max_clamp_p = (const float*)d_in[2];
    float4* out = (float4*)d_out;

    const int threads = 256;
    const int blocks = TOTAL_THREADS / threads;  // 6272, exact
    CGM_16707422781821_kernel<<<blocks, threads>>>(x, out, max_clamp_p);
}